// round 2
// baseline (speedup 1.0000x reference)
#include <cuda_runtime.h>
#include <math.h>

#define D    1024
#define HDIM 64
#define FF   2048
#define CATR 1280
#define KR   1408
#define SPLIT 1152

__device__ float g_cat [CATR * D];
__device__ float g_x   [CATR * D];
__device__ float g_q   [CATR * D];
__device__ float g_k   [KR   * D];
__device__ float g_v   [KR   * D];
__device__ float g_at  [CATR * D];
__device__ float g_t1  [CATR * FF];
__device__ float g_t2  [CATR * FF];
__device__ float g_cos [1280 * 32];
__device__ float g_sin [1280 * 32];

__device__ __forceinline__ unsigned long long pk2(float x, float y) {
    unsigned long long r; asm("mov.b64 %0, {%1, %2};" : "=l"(r) : "f"(x), "f"(y)); return r;
}
__device__ __forceinline__ void fma2(unsigned long long& d, unsigned long long a, unsigned long long b) {
    asm("fma.rn.f32x2 %0, %1, %2, %0;" : "+l"(d) : "l"(a), "l"(b));
}
__device__ __forceinline__ float2 upk2(unsigned long long v) {
    float2 r; asm("mov.b64 {%0, %1}, %2;" : "=f"(r.x), "=f"(r.y) : "l"(v)); return r;
}

__global__ void rope_setup_kernel(float* cs, float* sn) {
    int pos = blockIdx.x, i = threadIdx.x;
    double inv = 1.0 / pow(10000.0, (double)(2 * i) / 64.0);
    double ang = (double)pos * inv;
    cs[pos * 32 + i] = (float)cos(ang);
    sn[pos * 32 + i] = (float)sin(ang);
}

__global__ void __launch_bounds__(256) embed_kernel(const int* __restrict__ ids,
        const float* __restrict__ emb, const float* __restrict__ bcn,
        const float* __restrict__ fgt, float* __restrict__ cat) {
    int r = blockIdx.x, t = threadIdx.x;
    const float* src;
    if (r < 1024)      src = emb + (size_t)ids[r] * D;
    else if (r < 1152) src = bcn + (size_t)(r - 1024) * D;
    else               src = fgt + (size_t)(r - 1152) * D;
    *(float4*)(cat + (size_t)r * D + t * 4) = *(const float4*)(src + t * 4);
}

__global__ void __launch_bounds__(256) blend_kernel(const float* __restrict__ cat,
        const float* __restrict__ mem, float* __restrict__ out) {
    int m = blockIdx.x, c = threadIdx.x * 4;
    float4 fg = *(const float4*)(cat + (size_t)(1152 + m) * D + c);
    float4 bc = *(const float4*)(cat + (size_t)(1024 + m) * D + c);
    float4 mv = *(const float4*)(mem + (size_t)m * D + c);
    float4 o; float g;
    g = 1.f / (1.f + expf(-fg.x)); o.x = mv.x * g + bc.x * (1.f - g);
    g = 1.f / (1.f + expf(-fg.y)); o.y = mv.y * g + bc.y * (1.f - g);
    g = 1.f / (1.f + expf(-fg.z)); o.z = mv.z * g + bc.z * (1.f - g);
    g = 1.f / (1.f + expf(-fg.w)); o.w = mv.w * g + bc.w * (1.f - g);
    *(float4*)(out + (size_t)m * D + c) = o;
}

__global__ void __launch_bounds__(256) rms_kernel(const float* __restrict__ in,
        const float* __restrict__ w, float* __restrict__ out) {
    int row = blockIdx.x, t = threadIdx.x;
    float4 v = *(const float4*)(in + (size_t)row * D + t * 4);
    float ss = v.x * v.x + v.y * v.y + v.z * v.z + v.w * v.w;
    #pragma unroll
    for (int o = 16; o > 0; o >>= 1) ss += __shfl_xor_sync(0xffffffffu, ss, o);
    __shared__ float sb[8]; __shared__ float stot;
    if ((t & 31) == 0) sb[t >> 5] = ss;
    __syncthreads();
    if (t == 0) { float z = 0.f; for (int i = 0; i < 8; i++) z += sb[i]; stot = z; }
    __syncthreads();
    float r = rsqrtf(stot * (1.f / 1024.f) + 1e-5f);
    float4 wv = *(const float4*)(w + t * 4);
    float4 o = make_float4(v.x * wv.x * r, v.y * wv.y * r, v.z * wv.z * r, v.w * wv.w * r);
    *(float4*)(out + (size_t)row * D + t * 4) = o;
}

struct GD { const float* A; const float* W; float* C; };
struct GB { GD g[8]; };

// C[MxN] = A[MxK] @ W[KxN]  (optionally +=).  BM=64 BN=128 BK=16, 256 thr.
__global__ void __launch_bounds__(256) gemm_kernel(GB b, int M, int N, int K, int accFlag) {
    GD d = b.g[blockIdx.z];
    const float* A = d.A; const float* W = d.W; float* C = d.C;
    int m0 = blockIdx.y * 64, n0 = blockIdx.x * 128;
    __shared__ __align__(16) float As[16][68];
    __shared__ __align__(16) float Ws[16][128];
    int t = threadIdx.x, ty = t >> 4, tx = t & 15;
    unsigned long long acc[4][4];
    #pragma unroll
    for (int i = 0; i < 4; i++)
        #pragma unroll
        for (int j = 0; j < 4; j++) acc[i][j] = 0ull;
    int aRow = t >> 2, aCol = (t & 3) * 4;
    int wRow = t >> 4, wCol = (t & 15) * 4;
    const float* Ap = A + (size_t)(m0 + aRow) * K + aCol;
    const float* Wp = W + (size_t)wRow * N + n0 + wCol;
    for (int k0 = 0; k0 < K; k0 += 16) {
        float4 av = *(const float4*)(Ap + k0);
        float4 w0 = *(const float4*)(Wp + (size_t)k0 * N);
        float4 w1 = *(const float4*)(Wp + (size_t)k0 * N + 64);
        __syncthreads();
        As[aCol][aRow] = av.x; As[aCol + 1][aRow] = av.y;
        As[aCol + 2][aRow] = av.z; As[aCol + 3][aRow] = av.w;
        *(float4*)&Ws[wRow][wCol] = w0;
        *(float4*)&Ws[wRow][wCol + 64] = w1;
        __syncthreads();
        #pragma unroll
        for (int k = 0; k < 16; k++) {
            float4 a4 = *(const float4*)&As[k][ty * 4];
            ulonglong2 b0 = *(const ulonglong2*)&Ws[k][tx * 8];
            ulonglong2 b1 = *(const ulonglong2*)&Ws[k][tx * 8 + 4];
            unsigned long long ap;
            ap = pk2(a4.x, a4.x);
            fma2(acc[0][0], ap, b0.x); fma2(acc[0][1], ap, b0.y);
            fma2(acc[0][2], ap, b1.x); fma2(acc[0][3], ap, b1.y);
            ap = pk2(a4.y, a4.y);
            fma2(acc[1][0], ap, b0.x); fma2(acc[1][1], ap, b0.y);
            fma2(acc[1][2], ap, b1.x); fma2(acc[1][3], ap, b1.y);
            ap = pk2(a4.z, a4.z);
            fma2(acc[2][0], ap, b0.x); fma2(acc[2][1], ap, b0.y);
            fma2(acc[2][2], ap, b1.x); fma2(acc[2][3], ap, b1.y);
            ap = pk2(a4.w, a4.w);
            fma2(acc[3][0], ap, b0.x); fma2(acc[3][1], ap, b0.y);
            fma2(acc[3][2], ap, b1.x); fma2(acc[3][3], ap, b1.y);
        }
    }
    #pragma unroll
    for (int i = 0; i < 4; i++) {
        float* cp = C + (size_t)(m0 + ty * 4 + i) * N + n0 + tx * 8;
        float2 v0 = upk2(acc[i][0]), v1 = upk2(acc[i][1]);
        float2 v2 = upk2(acc[i][2]), v3 = upk2(acc[i][3]);
        float4 r0 = make_float4(v0.x, v0.y, v1.x, v1.y);
        float4 r1 = make_float4(v2.x, v2.y, v3.x, v3.y);
        if (accFlag) {
            float4 o0 = *(const float4*)cp; float4 o1 = *(const float4*)(cp + 4);
            r0.x += o0.x; r0.y += o0.y; r0.z += o0.z; r0.w += o0.w;
            r1.x += o1.x; r1.y += o1.y; r1.z += o1.z; r1.w += o1.w;
        }
        *(float4*)cp = r0; *(float4*)(cp + 4) = r1;
    }
}

// RoPE in place: blocks 0..1279 -> q rows, 1280..2687 -> k rows
__global__ void __launch_bounds__(512) rope_kernel(float* q, float* k,
        const float* __restrict__ cs, const float* __restrict__ sn) {
    int idx = blockIdx.x;
    float* buf; int r, pos;
    if (idx < 1280) { buf = q; r = idx; pos = (r < 1152) ? r + 128 : r; }
    else            { buf = k; r = idx - 1280; pos = (r < 1280) ? r : r - 128; }
    int t = threadIdx.x, h = t >> 5, j = t & 31;
    float* p = buf + (size_t)r * D + h * HDIM;
    float x0 = p[j], x1 = p[j + 32];
    float c = cs[pos * 32 + j], s = sn[pos * 32 + j];
    p[j] = x0 * c - x1 * s;
    p[j + 32] = x1 * c + x0 * s;
}

// fused flash attention: key j valid iff j <= qi + off; keys j>=SPLIT from K2/V2
struct AD { const float* Q; const float* K2; const float* V2; float* O; int nq; int off; };
struct AA { const float* K1; const float* V1; AD d[3]; };

__global__ void __launch_bounds__(256) attn_kernel(AA args) {
    AD ad = args.d[blockIdx.z];
    int q0 = blockIdx.x * 64;
    if (q0 >= ad.nq) return;
    int h = blockIdx.y;
    __shared__ __align__(16) float Qs[64][68];
    __shared__ __align__(16) float Ks[32][68];
    __shared__ __align__(16) float Vs[32][68];
    __shared__ __align__(16) float Ps[64][36];
    int t = threadIdx.x;
    {
        int col = (t & 15) * 4, rb = t >> 4;
        #pragma unroll
        for (int rr = 0; rr < 4; rr++) {
            int row = rb + rr * 16;
            float4 v = *(const float4*)(ad.Q + (size_t)(q0 + row) * D + h * HDIM + col);
            v.x *= 0.125f; v.y *= 0.125f; v.z *= 0.125f; v.w *= 0.125f;
            *(float4*)&Qs[row][col] = v;
        }
    }
    int qy = t >> 2, kq = t & 3;
    int qi = q0 + qy;
    float O[16];
    #pragma unroll
    for (int i = 0; i < 16; i++) O[i] = 0.f;
    float mM = -1e30f, lS = 0.f;
    int nk = ad.off + ad.nq;
    int jmax = min(nk, q0 + 64 + ad.off);
    for (int j0 = 0; j0 < jmax; j0 += 32) {
        __syncthreads();
        {
            int jr = t >> 3, cc = (t & 7) * 8;
            int j = j0 + jr;
            if (j < nk) {
                const float* kp = (j < SPLIT) ? (args.K1 + (size_t)j * D) : (ad.K2 + (size_t)(j - SPLIT) * D);
                const float* vp = (j < SPLIT) ? (args.V1 + (size_t)j * D) : (ad.V2 + (size_t)(j - SPLIT) * D);
                *(float4*)&Ks[jr][cc]     = *(const float4*)(kp + h * HDIM + cc);
                *(float4*)&Ks[jr][cc + 4] = *(const float4*)(kp + h * HDIM + cc + 4);
                *(float4*)&Vs[jr][cc]     = *(const float4*)(vp + h * HDIM + cc);
                *(float4*)&Vs[jr][cc + 4] = *(const float4*)(vp + h * HDIM + cc + 4);
            } else {
                float4 z = make_float4(0.f, 0.f, 0.f, 0.f);
                *(float4*)&Ks[jr][cc] = z; *(float4*)&Ks[jr][cc + 4] = z;
                *(float4*)&Vs[jr][cc] = z; *(float4*)&Vs[jr][cc + 4] = z;
            }
        }
        __syncthreads();
        float s[8];
        #pragma unroll
        for (int jj = 0; jj < 8; jj++) s[jj] = 0.f;
        #pragma unroll
        for (int d4 = 0; d4 < 16; d4++) {
            float4 qv = *(const float4*)&Qs[qy][d4 * 4];
            #pragma unroll
            for (int jj = 0; jj < 8; jj++) {
                float4 kv = *(const float4*)&Ks[kq * 8 + jj][d4 * 4];
                s[jj] += qv.x * kv.x + qv.y * kv.y + qv.z * kv.z + qv.w * kv.w;
            }
        }
        #pragma unroll
        for (int jj = 0; jj < 8; jj++) {
            int j = j0 + kq * 8 + jj;
            if (j > qi + ad.off) s[jj] = -1e30f;
        }
        float tm = s[0];
        #pragma unroll
        for (int jj = 1; jj < 8; jj++) tm = fmaxf(tm, s[jj]);
        tm = fmaxf(tm, __shfl_xor_sync(0xffffffffu, tm, 1));
        tm = fmaxf(tm, __shfl_xor_sync(0xffffffffu, tm, 2));
        float mn = fmaxf(mM, tm);
        float p[8], ps = 0.f;
        #pragma unroll
        for (int jj = 0; jj < 8; jj++) { p[jj] = __expf(s[jj] - mn); ps += p[jj]; }
        ps += __shfl_xor_sync(0xffffffffu, ps, 1);
        ps += __shfl_xor_sync(0xffffffffu, ps, 2);
        float alpha = __expf(mM - mn);
        lS = lS * alpha + ps;
        mM = mn;
        #pragma unroll
        for (int i = 0; i < 16; i++) O[i] *= alpha;
        #pragma unroll
        for (int jj = 0; jj < 8; jj++) Ps[qy][kq * 8 + jj] = p[jj];
        __syncthreads();
        #pragma unroll 8
        for (int j = 0; j < 32; j++) {
            float pv = Ps[qy][j];
            float4 v0 = *(const float4*)&Vs[j][kq * 16];
            float4 v1 = *(const float4*)&Vs[j][kq * 16 + 4];
            float4 v2 = *(const float4*)&Vs[j][kq * 16 + 8];
            float4 v3 = *(const float4*)&Vs[j][kq * 16 + 12];
            O[0]  += pv * v0.x; O[1]  += pv * v0.y; O[2]  += pv * v0.z; O[3]  += pv * v0.w;
            O[4]  += pv * v1.x; O[5]  += pv * v1.y; O[6]  += pv * v1.z; O[7]  += pv * v1.w;
            O[8]  += pv * v2.x; O[9]  += pv * v2.y; O[10] += pv * v2.z; O[11] += pv * v2.w;
            O[12] += pv * v3.x; O[13] += pv * v3.y; O[14] += pv * v3.z; O[15] += pv * v3.w;
        }
    }
    float inv = 1.f / lS;
    float* op = ad.O + (size_t)qi * D + h * HDIM + kq * 16;
    #pragma unroll
    for (int i = 0; i < 16; i += 4)
        *(float4*)(op + i) = make_float4(O[i] * inv, O[i+1] * inv, O[i+2] * inv, O[i+3] * inv);
}

__global__ void __launch_bounds__(256) silu_kernel(float* t1, const float* __restrict__ t2) {
    int i = (blockIdx.x * 256 + threadIdx.x) * 4;
    float4 a = *(const float4*)(t1 + i);
    float4 b = *(const float4*)(t2 + i);
    float4 o;
    o.x = (a.x / (1.f + expf(-a.x))) * b.x;
    o.y = (a.y / (1.f + expf(-a.y))) * b.y;
    o.z = (a.z / (1.f + expf(-a.z))) * b.z;
    o.w = (a.w / (1.f + expf(-a.w))) * b.w;
    *(float4*)(t1 + i) = o;
}

extern "C" void kernel_launch(void* const* d_in, const int* in_sizes, int n_in,
                              void* d_out, int out_size) {
    const int*   ids    = (const int*)  d_in[0];
    const float* memory = (const float*)d_in[1];
    const float* beacon = (const float*)d_in[2];
    const float* forget = (const float*)d_in[3];
    const float* embedW = (const float*)d_in[4];
    const float* ln1    = (const float*)d_in[5];
    const float* ln2    = (const float*)d_in[6];
    const float* Wq  = (const float*)d_in[7];
    const float* Wk  = (const float*)d_in[8];
    const float* Wv  = (const float*)d_in[9];
    const float* Wo  = (const float*)d_in[10];
    const float* mWk = (const float*)d_in[11];
    const float* mWv = (const float*)d_in[12];
    const float* bWq = (const float*)d_in[13];
    const float* bWk = (const float*)d_in[14];
    const float* bWv = (const float*)d_in[15];
    const float* fWq = (const float*)d_in[16];
    const float* fWk = (const float*)d_in[17];
    const float* fWv = (const float*)d_in[18];
    const float* Wg  = (const float*)d_in[19];
    const float* Wu  = (const float*)d_in[20];
    const float* Wd  = (const float*)d_in[21];
    float* out = (float*)d_out;

    float *cat, *x, *q, *k, *v, *at, *t1, *t2, *cs, *sn;
    cudaGetSymbolAddress((void**)&cat, g_cat);
    cudaGetSymbolAddress((void**)&x,   g_x);
    cudaGetSymbolAddress((void**)&q,   g_q);
    cudaGetSymbolAddress((void**)&k,   g_k);
    cudaGetSymbolAddress((void**)&v,   g_v);
    cudaGetSymbolAddress((void**)&at,  g_at);
    cudaGetSymbolAddress((void**)&t1,  g_t1);
    cudaGetSymbolAddress((void**)&t2,  g_t2);
    cudaGetSymbolAddress((void**)&cs,  g_cos);
    cudaGetSymbolAddress((void**)&sn,  g_sin);

    rope_setup_kernel<<<1280, 32>>>(cs, sn);
    embed_kernel<<<1280, 256>>>(ids, embedW, beacon, forget, cat);

    const size_t DD = (size_t)D * D;
    const size_t MD = (size_t)128 * D;

    for (int l = 0; l < 8; l++) {
        // scan records (beacon, forget) at step ENTRY -> emit output slab l now
        blend_kernel<<<128, 256>>>(cat, memory + (size_t)l * MD, out + (size_t)l * MD);
        if (l == 7) break;  // layer 7 compute is dead code

        rms_kernel<<<1280, 256>>>(cat, ln1 + (size_t)l * D, x);

        GB bb;
        bb.g[0] = { x, Wq + l * DD, q };
        bb.g[1] = { x, Wk + l * DD, k + 128 * D };
        bb.g[2] = { x, Wv + l * DD, v + 128 * D };
        gemm_kernel<<<dim3(8, 16, 3), 256>>>(bb, 1024, 1024, 1024, 0);

        GB sb;
        const float* meml = memory + (size_t)l * MD;
        const float* xb = x + 1024 * D;
        const float* xf = x + 1152 * D;
        sb.g[0] = { meml, mWk + l * DD, k };
        sb.g[1] = { meml, mWv + l * DD, v };
        sb.g[2] = { xb, bWq + l * DD, q + 1024 * D };
        sb.g[3] = { xb, bWk + l * DD, k + 1152 * D };
        sb.g[4] = { xb, bWv + l * DD, v + 1152 * D };
        sb.g[5] = { xf, fWq + l * DD, q + 1152 * D };
        sb.g[6] = { xf, fWk + l * DD, k + 1280 * D };
        sb.g[7] = { xf, fWv + l * DD, v + 1280 * D };
        gemm_kernel<<<dim3(8, 2, 8), 256>>>(sb, 128, 1024, 1024, 0);

        rope_kernel<<<2688, 512>>>(q, k, cs, sn);

        AA aa;
        aa.K1 = k; aa.V1 = v;
        aa.d[0] = { q,            (const float*)0, (const float*)0, at,            1024, 128  };
        aa.d[1] = { q + 1024 * D, k + 1152 * D,    v + 1152 * D,    at + 1024 * D, 128,  1152 };
        aa.d[2] = { q + 1152 * D, k + 1280 * D,    v + 1280 * D,    at + 1152 * D, 128,  1152 };
        attn_kernel<<<dim3(16, 16, 3), 256>>>(aa);

        GB ob; ob.g[0] = { at, Wo + l * DD, cat };
        gemm_kernel<<<dim3(8, 20, 1), 256>>>(ob, 1280, 1024, 1024, 1);

        rms_kernel<<<1280, 256>>>(cat, ln2 + (size_t)l * D, x);

        GB mb;
        mb.g[0] = { x, Wg + (size_t)l * D * FF, t1 };
        mb.g[1] = { x, Wu + (size_t)l * D * FF, t2 };
        gemm_kernel<<<dim3(16, 20, 2), 256>>>(mb, 1280, 2048, 1024, 0);

        silu_kernel<<<CATR * FF / 1024, 256>>>(t1, t2);

        GB db; db.g[0] = { t1, Wd + (size_t)l * FF * D, cat };
        gemm_kernel<<<dim3(8, 20, 1), 256>>>(db, 1280, 1024, 2048, 1);
    }
}

// round 10
// speedup vs baseline: 1.3833x; 1.3833x over previous
#include <cuda_runtime.h>
#include <cuda_bf16.h>
#include <cstdint>
#include <math.h>

typedef unsigned int u32;
typedef unsigned long long u64;

#define D    1024
#define HDIM 64
#define FF   2048
#define CATR 1280
#define KR   1408
#define SPLITK 1152

// ---------------- scratch (device globals) ----------------
__device__ float g_cat[CATR * D];
__device__ __nv_bfloat16 g_xhi[CATR * D];
__device__ __nv_bfloat16 g_xlo[CATR * D];
__device__ float g_q[CATR * D];
__device__ float g_k[KR * D];
__device__ float g_v[KR * D];
__device__ __nv_bfloat16 g_athi[CATR * D];
__device__ __nv_bfloat16 g_atlo[CATR * D];
__device__ float g_t1[CATR * FF];
__device__ float g_t2[CATR * FF];
__device__ __nv_bfloat16 g_t1hi[CATR * FF];
__device__ __nv_bfloat16 g_t1lo[CATR * FF];
__device__ __nv_bfloat16 g_mhi[128 * D];
__device__ __nv_bfloat16 g_mlo[128 * D];
__device__ float g_cosT[1280 * 32];
__device__ float g_sinT[1280 * 32];
#define WLAYER 18874368ull
__device__ __nv_bfloat16 g_whi[7 * WLAYER];
__device__ __nv_bfloat16 g_wlo[7 * WLAYER];

// ---------------- helpers ----------------
__device__ __forceinline__ u32 smem_u32(const void* p) {
    u32 a;
    asm("{ .reg .u64 t; cvta.to.shared.u64 t, %1; cvt.u32.u64 %0, t; }" : "=r"(a) : "l"(p));
    return a;
}

__device__ __forceinline__ void ldsm4(u32* r, u32 addr) {
    asm volatile("ldmatrix.sync.aligned.m8n8.x4.shared.b16 {%0, %1, %2, %3}, [%4];"
        : "=r"(r[0]), "=r"(r[1]), "=r"(r[2]), "=r"(r[3]) : "r"(addr));
}

__device__ __forceinline__ void mma_bf16(float* c, const u32* a, const u32* b) {
    asm volatile("mma.sync.aligned.m16n8k16.row.col.f32.bf16.bf16.f32 "
        "{%0, %1, %2, %3}, {%4, %5, %6, %7}, {%8, %9}, {%0, %1, %2, %3};"
        : "+f"(c[0]), "+f"(c[1]), "+f"(c[2]), "+f"(c[3])
        : "r"(a[0]), "r"(a[1]), "r"(a[2]), "r"(a[3]), "r"(b[0]), "r"(b[1]));
}

__device__ __forceinline__ void split_store(__nv_bfloat16* hi, __nv_bfloat16* lo, size_t i, float v) {
    __nv_bfloat16 h = __float2bfloat16(v);
    hi[i] = h;
    lo[i] = __float2bfloat16(v - __bfloat162float(h));
}

// ---------------- small kernels ----------------
__global__ void rope_setup_kernel(float* cs, float* sn) {
    int pos = blockIdx.x;
    int i = threadIdx.x;
    double inv = 1.0 / pow(10000.0, (double)(2 * i) / 64.0);
    double ang = (double)pos * inv;
    cs[pos * 32 + i] = (float)cos(ang);
    sn[pos * 32 + i] = (float)sin(ang);
}

__global__ void __launch_bounds__(256) embed_kernel(const int* __restrict__ ids,
        const float* __restrict__ emb, const float* __restrict__ bcn,
        const float* __restrict__ fgt, float* __restrict__ cat) {
    int r = blockIdx.x;
    int t = threadIdx.x;
    const float* src;
    if (r < 1024)      src = emb + (size_t)ids[r] * D;
    else if (r < 1152) src = bcn + (size_t)(r - 1024) * D;
    else               src = fgt + (size_t)(r - 1152) * D;
    *(float4*)(cat + (size_t)r * D + t * 4) = *(const float4*)(src + t * 4);
}

__global__ void __launch_bounds__(256) blend_kernel(const float* __restrict__ cat,
        const float* __restrict__ mem, float* __restrict__ out) {
    int m = blockIdx.x;
    int c = threadIdx.x * 4;
    float4 fg = *(const float4*)(cat + (size_t)(1152 + m) * D + c);
    float4 bc = *(const float4*)(cat + (size_t)(1024 + m) * D + c);
    float4 mv = *(const float4*)(mem + (size_t)m * D + c);
    float4 o;
    float g;
    g = 1.0f / (1.0f + expf(-fg.x)); o.x = mv.x * g + bc.x * (1.0f - g);
    g = 1.0f / (1.0f + expf(-fg.y)); o.y = mv.y * g + bc.y * (1.0f - g);
    g = 1.0f / (1.0f + expf(-fg.z)); o.z = mv.z * g + bc.z * (1.0f - g);
    g = 1.0f / (1.0f + expf(-fg.w)); o.w = mv.w * g + bc.w * (1.0f - g);
    *(float4*)(out + (size_t)m * D + c) = o;
}

__global__ void __launch_bounds__(256) rms_kernel(const float* __restrict__ in,
        const float* __restrict__ w, __nv_bfloat16* __restrict__ xhi, __nv_bfloat16* __restrict__ xlo) {
    int row = blockIdx.x;
    int t = threadIdx.x;
    float4 v = *(const float4*)(in + (size_t)row * D + t * 4);
    float ss = v.x * v.x + v.y * v.y + v.z * v.z + v.w * v.w;
    #pragma unroll
    for (int o = 16; o > 0; o >>= 1) ss += __shfl_xor_sync(0xffffffffu, ss, o);
    __shared__ float sred[8];
    __shared__ float stot;
    if ((t & 31) == 0) sred[t >> 5] = ss;
    __syncthreads();
    if (t == 0) {
        float z = 0.0f;
        for (int i = 0; i < 8; i++) z += sred[i];
        stot = z;
    }
    __syncthreads();
    float r = rsqrtf(stot * (1.0f / 1024.0f) + 1e-5f);
    float4 wv = *(const float4*)(w + t * 4);
    size_t base = (size_t)row * D + t * 4;
    split_store(xhi, xlo, base + 0, v.x * wv.x * r);
    split_store(xhi, xlo, base + 1, v.y * wv.y * r);
    split_store(xhi, xlo, base + 2, v.z * wv.z * r);
    split_store(xhi, xlo, base + 3, v.w * wv.w * r);
}

__global__ void __launch_bounds__(256) memcvt_kernel(const float* __restrict__ mem,
        __nv_bfloat16* __restrict__ hi, __nv_bfloat16* __restrict__ lo) {
    int r = blockIdx.x;
    int t = threadIdx.x;
    size_t base = (size_t)r * D + t * 4;
    #pragma unroll
    for (int i = 0; i < 4; i++) split_store(hi, lo, base + i, mem[base + i]);
}

__global__ void __launch_bounds__(256) wsplit_kernel(const float* __restrict__ src,
        __nv_bfloat16* __restrict__ hi, __nv_bfloat16* __restrict__ lo, int N, int K) {
    __shared__ float tile[32][33];
    int n0 = blockIdx.x * 32;
    int k0 = blockIdx.y * 32;
    int tx = threadIdx.x & 31;
    int ty = threadIdx.x >> 5;
    #pragma unroll
    for (int j = 0; j < 4; j++)
        tile[ty + 8 * j][tx] = src[(size_t)(k0 + ty + 8 * j) * N + n0 + tx];
    __syncthreads();
    #pragma unroll
    for (int j = 0; j < 4; j++) {
        int nr = ty + 8 * j;
        split_store(hi, lo, (size_t)(n0 + nr) * K + k0 + tx, tile[tx][nr]);
    }
}

// ---------------- mma.sync GEMM: C[M,N] = (Ahi+Alo) @ (Whi+Wlo)^T ----------------
// A: [M][K] K-major hi/lo bf16.  W: [N][K] K-major hi/lo bf16.
// CTA tile 128x128, 8 warps (2x4), warp tile 64x32, BK=32, double-buffered smem.
// smem per buffer: Ah(10240) Al(10240) Bh(10240) Bl(10240) = 40960B, row pitch 80B.
struct TGD { const __nv_bfloat16* ahi; const __nv_bfloat16* alo;
             const __nv_bfloat16* whi; const __nv_bfloat16* wlo; float* c; };
struct TGB { TGD g[8]; };

#define SM_BUF 40960
#define PITCH  80

__global__ void __launch_bounds__(256, 1) tcgemm_kernel(TGB b, int N, int K, int acc) {
    TGD dd = b.g[blockIdx.z];
    int m0 = blockIdx.y * 128;
    int n0 = blockIdx.x * 128;
    extern __shared__ __align__(16) char smem[];
    u32 smb = smem_u32(smem);

    int t = threadIdx.x;
    int lane = t & 31;
    int wid = t >> 5;
    int wm = (wid >> 2) * 64;
    int wn = (wid & 3) * 32;

    // gmem->smem mapping: thread covers row lr (0..127), 2x16B at byte cols lh*32 + i*16
    int lr = t >> 1;
    int lh = t & 1;
    const __nv_bfloat16* pAh = dd.ahi + (size_t)(m0 + lr) * K + lh * 16;
    const __nv_bfloat16* pAl = dd.alo + (size_t)(m0 + lr) * K + lh * 16;
    const __nv_bfloat16* pBh = dd.whi + (size_t)(n0 + lr) * K + lh * 16;
    const __nv_bfloat16* pBl = dd.wlo + (size_t)(n0 + lr) * K + lh * 16;
    int so = lr * PITCH + lh * 32;

    float accf[4][4][4];
    #pragma unroll
    for (int mt = 0; mt < 4; mt++)
        #pragma unroll
        for (int nt = 0; nt < 4; nt++)
            #pragma unroll
            for (int i = 0; i < 4; i++) accf[mt][nt][i] = 0.0f;

    int nch = K / 32;

    // preload chunk 0 into buffer 0
    {
        char* dst = smem;
        #pragma unroll
        for (int i = 0; i < 2; i++) {
            *(uint4*)(dst + so + i * 16)         = *(const uint4*)(pAh + i * 8);
            *(uint4*)(dst + 10240 + so + i * 16) = *(const uint4*)(pAl + i * 8);
            *(uint4*)(dst + 20480 + so + i * 16) = *(const uint4*)(pBh + i * 8);
            *(uint4*)(dst + 30720 + so + i * 16) = *(const uint4*)(pBl + i * 8);
        }
    }
    __syncthreads();

    u32 lrow = (u32)(lane & 15);
    u32 lc16 = (u32)((lane >> 4) * 16);

    for (int c = 0; c < nch; c++) {
        int cur = c & 1;
        uint4 pf[8];
        if (c + 1 < nch) {
            size_t ko = (size_t)(c + 1) * 32;
            #pragma unroll
            for (int i = 0; i < 2; i++) {
                pf[i]     = *(const uint4*)(pAh + ko + i * 8);
                pf[2 + i] = *(const uint4*)(pAl + ko + i * 8);
                pf[4 + i] = *(const uint4*)(pBh + ko + i * 8);
                pf[6 + i] = *(const uint4*)(pBl + ko + i * 8);
            }
        }
        u32 bufb = smb + cur * SM_BUF;
        #pragma unroll
        for (int ks = 0; ks < 2; ks++) {
            u32 kb = ks * 32;
            u32 ah[4][4], al[4][4], bh[4][2], bl[4][2];
            #pragma unroll
            for (int mt = 0; mt < 4; mt++) {
                u32 addr = bufb + (wm + mt * 16 + lrow) * PITCH + kb + lc16;
                ldsm4(ah[mt], addr);
                ldsm4(al[mt], addr + 10240);
            }
            #pragma unroll
            for (int p = 0; p < 2; p++) {
                u32 raw[4];
                u32 addr = bufb + 20480 + (wn + p * 16 + lrow) * PITCH + kb + lc16;
                ldsm4(raw, addr);
                bh[p * 2][0] = raw[0]; bh[p * 2][1] = raw[2];
                bh[p * 2 + 1][0] = raw[1]; bh[p * 2 + 1][1] = raw[3];
                ldsm4(raw, addr + 10240);
                bl[p * 2][0] = raw[0]; bl[p * 2][1] = raw[2];
                bl[p * 2 + 1][0] = raw[1]; bl[p * 2 + 1][1] = raw[3];
            }
            #pragma unroll
            for (int mt = 0; mt < 4; mt++) {
                #pragma unroll
                for (int nt = 0; nt < 4; nt++) {
                    mma_bf16(accf[mt][nt], ah[mt], bh[nt]);
                    mma_bf16(accf[mt][nt], ah[mt], bl[nt]);
                    mma_bf16(accf[mt][nt], al[mt], bh[nt]);
                }
            }
        }
        if (c + 1 < nch) {
            char* dst = smem + (cur ^ 1) * SM_BUF;
            #pragma unroll
            for (int i = 0; i < 2; i++) {
                *(uint4*)(dst + so + i * 16)         = pf[i];
                *(uint4*)(dst + 10240 + so + i * 16) = pf[2 + i];
                *(uint4*)(dst + 20480 + so + i * 16) = pf[4 + i];
                *(uint4*)(dst + 30720 + so + i * 16) = pf[6 + i];
            }
        }
        __syncthreads();
    }

    // epilogue: direct register -> gmem
    int r0 = lane >> 2;
    int c0 = (lane & 3) * 2;
    #pragma unroll
    for (int mt = 0; mt < 4; mt++) {
        #pragma unroll
        for (int nt = 0; nt < 4; nt++) {
            int row = m0 + wm + mt * 16 + r0;
            int col = n0 + wn + nt * 8 + c0;
            float* p0 = dd.c + (size_t)row * N + col;
            float* p1 = dd.c + (size_t)(row + 8) * N + col;
            float2 v0, v1;
            v0.x = accf[mt][nt][0]; v0.y = accf[mt][nt][1];
            v1.x = accf[mt][nt][2]; v1.y = accf[mt][nt][3];
            if (acc) {
                float2 o0 = *(const float2*)p0;
                float2 o1 = *(const float2*)p1;
                v0.x += o0.x; v0.y += o0.y;
                v1.x += o1.x; v1.y += o1.y;
            }
            *(float2*)p0 = v0;
            *(float2*)p1 = v1;
        }
    }
}

// ---------------- rope ----------------
__global__ void __launch_bounds__(512) rope_kernel(float* q, float* k,
        const float* __restrict__ cs, const float* __restrict__ sn) {
    int idx = blockIdx.x;
    float* buf;
    int r, pos;
    if (idx < 1280) { buf = q; r = idx; pos = (r < 1152) ? r + 128 : r; }
    else            { buf = k; r = idx - 1280; pos = (r < 1280) ? r : r - 128; }
    int t = threadIdx.x;
    int h = t >> 5;
    int j = t & 31;
    float* p = buf + (size_t)r * D + h * HDIM;
    float x0 = p[j];
    float x1 = p[j + 32];
    float c = cs[pos * 32 + j];
    float s = sn[pos * 32 + j];
    p[j] = x0 * c - x1 * s;
    p[j + 32] = x1 * c + x0 * s;
}

// ---------------- fused flash attention ----------------
struct AD { const float* Q; const float* K2; const float* V2;
            __nv_bfloat16* Ohi; __nv_bfloat16* Olo; int nq; int off; };
struct AA { const float* K1; const float* V1; AD d[3]; };

__global__ void __launch_bounds__(256) attn_kernel(AA args) {
    AD ad = args.d[blockIdx.z];
    int q0 = blockIdx.x * 64;
    if (q0 >= ad.nq) return;
    int h = blockIdx.y;
    __shared__ __align__(16) float Qs[64][68];
    __shared__ __align__(16) float Ks[32][68];
    __shared__ __align__(16) float Vs[32][68];
    __shared__ __align__(16) float Ps[64][36];
    int t = threadIdx.x;
    {
        int col = (t & 15) * 4;
        int rb = t >> 4;
        #pragma unroll
        for (int rr = 0; rr < 4; rr++) {
            int row = rb + rr * 16;
            float4 v = *(const float4*)(ad.Q + (size_t)(q0 + row) * D + h * HDIM + col);
            v.x *= 0.125f; v.y *= 0.125f; v.z *= 0.125f; v.w *= 0.125f;
            *(float4*)&Qs[row][col] = v;
        }
    }
    int qy = t >> 2;
    int kq = t & 3;
    int qi = q0 + qy;
    float O[16];
    #pragma unroll
    for (int i = 0; i < 16; i++) O[i] = 0.0f;
    float mM = -1e30f, lS = 0.0f;
    int nk = ad.off + ad.nq;
    int jmax = min(nk, q0 + 64 + ad.off);
    for (int j0 = 0; j0 < jmax; j0 += 32) {
        __syncthreads();
        {
            int jr = t >> 3;
            int cc = (t & 7) * 8;
            int j = j0 + jr;
            if (j < nk) {
                const float* kp = (j < SPLITK) ? (args.K1 + (size_t)j * D) : (ad.K2 + (size_t)(j - SPLITK) * D);
                const float* vp = (j < SPLITK) ? (args.V1 + (size_t)j * D) : (ad.V2 + (size_t)(j - SPLITK) * D);
                *(float4*)&Ks[jr][cc]     = *(const float4*)(kp + h * HDIM + cc);
                *(float4*)&Ks[jr][cc + 4] = *(const float4*)(kp + h * HDIM + cc + 4);
                *(float4*)&Vs[jr][cc]     = *(const float4*)(vp + h * HDIM + cc);
                *(float4*)&Vs[jr][cc + 4] = *(const float4*)(vp + h * HDIM + cc + 4);
            } else {
                float4 z = make_float4(0.0f, 0.0f, 0.0f, 0.0f);
                *(float4*)&Ks[jr][cc] = z;
                *(float4*)&Ks[jr][cc + 4] = z;
                *(float4*)&Vs[jr][cc] = z;
                *(float4*)&Vs[jr][cc + 4] = z;
            }
        }
        __syncthreads();
        float s[8];
        #pragma unroll
        for (int jj = 0; jj < 8; jj++) s[jj] = 0.0f;
        #pragma unroll
        for (int d4 = 0; d4 < 16; d4++) {
            float4 qv = *(const float4*)&Qs[qy][d4 * 4];
            #pragma unroll
            for (int jj = 0; jj < 8; jj++) {
                float4 kv = *(const float4*)&Ks[kq * 8 + jj][d4 * 4];
                s[jj] += qv.x * kv.x + qv.y * kv.y + qv.z * kv.z + qv.w * kv.w;
            }
        }
        #pragma unroll
        for (int jj = 0; jj < 8; jj++) {
            int j = j0 + kq * 8 + jj;
            if (j > qi + ad.off) s[jj] = -1e30f;
        }
        float tmax = s[0];
        #pragma unroll
        for (int jj = 1; jj < 8; jj++) tmax = fmaxf(tmax, s[jj]);
        tmax = fmaxf(tmax, __shfl_xor_sync(0xffffffffu, tmax, 1));
        tmax = fmaxf(tmax, __shfl_xor_sync(0xffffffffu, tmax, 2));
        float mn = fmaxf(mM, tmax);
        float p[8], ps = 0.0f;
        #pragma unroll
        for (int jj = 0; jj < 8; jj++) { p[jj] = __expf(s[jj] - mn); ps += p[jj]; }
        ps += __shfl_xor_sync(0xffffffffu, ps, 1);
        ps += __shfl_xor_sync(0xffffffffu, ps, 2);
        float alpha = __expf(mM - mn);
        lS = lS * alpha + ps;
        mM = mn;
        #pragma unroll
        for (int i = 0; i < 16; i++) O[i] *= alpha;
        #pragma unroll
        for (int jj = 0; jj < 8; jj++) Ps[qy][kq * 8 + jj] = p[jj];
        __syncthreads();
        #pragma unroll 8
        for (int j = 0; j < 32; j++) {
            float pv = Ps[qy][j];
            float4 v0 = *(const float4*)&Vs[j][kq * 16];
            float4 v1 = *(const float4*)&Vs[j][kq * 16 + 4];
            float4 v2 = *(const float4*)&Vs[j][kq * 16 + 8];
            float4 v3 = *(const float4*)&Vs[j][kq * 16 + 12];
            O[0]  += pv * v0.x; O[1]  += pv * v0.y; O[2]  += pv * v0.z; O[3]  += pv * v0.w;
            O[4]  += pv * v1.x; O[5]  += pv * v1.y; O[6]  += pv * v1.z; O[7]  += pv * v1.w;
            O[8]  += pv * v2.x; O[9]  += pv * v2.y; O[10] += pv * v2.z; O[11] += pv * v2.w;
            O[12] += pv * v3.x; O[13] += pv * v3.y; O[14] += pv * v3.z; O[15] += pv * v3.w;
        }
    }
    float inv = 1.0f / lS;
    size_t base = (size_t)qi * D + h * HDIM + kq * 16;
    #pragma unroll
    for (int i = 0; i < 16; i++) split_store(ad.Ohi, ad.Olo, base + i, O[i] * inv);
}

__global__ void __launch_bounds__(256) silu_kernel(const float* __restrict__ t1,
        const float* __restrict__ t2, __nv_bfloat16* __restrict__ hi, __nv_bfloat16* __restrict__ lo) {
    size_t i = ((size_t)blockIdx.x * 256 + threadIdx.x) * 4;
    float4 a = *(const float4*)(t1 + i);
    float4 b = *(const float4*)(t2 + i);
    split_store(hi, lo, i + 0, (a.x / (1.0f + expf(-a.x))) * b.x);
    split_store(hi, lo, i + 1, (a.y / (1.0f + expf(-a.y))) * b.y);
    split_store(hi, lo, i + 2, (a.z / (1.0f + expf(-a.z))) * b.z);
    split_store(hi, lo, i + 3, (a.w / (1.0f + expf(-a.w))) * b.w);
}

// ---------------- host ----------------
extern "C" void kernel_launch(void* const* d_in, const int* in_sizes, int n_in,
                              void* d_out, int out_size) {
    const int*   ids    = (const int*)  d_in[0];
    const float* memory = (const float*)d_in[1];
    const float* beacon = (const float*)d_in[2];
    const float* forget = (const float*)d_in[3];
    const float* embedW = (const float*)d_in[4];
    const float* ln1    = (const float*)d_in[5];
    const float* ln2    = (const float*)d_in[6];
    const float* Wsrc[12] = { (const float*)d_in[7],  (const float*)d_in[8],  (const float*)d_in[9],
                              (const float*)d_in[10], (const float*)d_in[11], (const float*)d_in[12],
                              (const float*)d_in[13], (const float*)d_in[14], (const float*)d_in[15],
                              (const float*)d_in[16], (const float*)d_in[17], (const float*)d_in[18] };
    const float* Wg = (const float*)d_in[19];
    const float* Wu = (const float*)d_in[20];
    const float* Wd = (const float*)d_in[21];
    float* out = (float*)d_out;

    float *cat, *q, *k, *v, *t1, *t2, *cs, *sn;
    __nv_bfloat16 *xhi, *xlo, *athi, *atlo, *t1hi, *t1lo, *mhi, *mlo, *whi, *wlo;
    cudaGetSymbolAddress((void**)&cat,  g_cat);
    cudaGetSymbolAddress((void**)&xhi,  g_xhi);
    cudaGetSymbolAddress((void**)&xlo,  g_xlo);
    cudaGetSymbolAddress((void**)&q,    g_q);
    cudaGetSymbolAddress((void**)&k,    g_k);
    cudaGetSymbolAddress((void**)&v,    g_v);
    cudaGetSymbolAddress((void**)&athi, g_athi);
    cudaGetSymbolAddress((void**)&atlo, g_atlo);
    cudaGetSymbolAddress((void**)&t1,   g_t1);
    cudaGetSymbolAddress((void**)&t2,   g_t2);
    cudaGetSymbolAddress((void**)&t1hi, g_t1hi);
    cudaGetSymbolAddress((void**)&t1lo, g_t1lo);
    cudaGetSymbolAddress((void**)&mhi,  g_mhi);
    cudaGetSymbolAddress((void**)&mlo,  g_mlo);
    cudaGetSymbolAddress((void**)&whi,  g_whi);
    cudaGetSymbolAddress((void**)&wlo,  g_wlo);
    cudaGetSymbolAddress((void**)&cs,   g_cosT);
    cudaGetSymbolAddress((void**)&sn,   g_sinT);

    cudaFuncSetAttribute(tcgemm_kernel, cudaFuncAttributeMaxDynamicSharedMemorySize, 2 * SM_BUF);

    const size_t DD = (size_t)D * D;
    const size_t MD = (size_t)128 * D;
    const size_t OW = 1048576;
    const int SMSZ = 2 * SM_BUF;

    rope_setup_kernel<<<1280, 32>>>(cs, sn);
    embed_kernel<<<1280, 256>>>(ids, embedW, beacon, forget, cat);

    for (int l = 0; l < 7; l++) {
        size_t B0 = (size_t)l * WLAYER;
        for (int wi = 0; wi < 12; wi++)
            wsplit_kernel<<<dim3(32, 32), 256>>>(Wsrc[wi] + l * DD, whi + B0 + wi * OW, wlo + B0 + wi * OW, 1024, 1024);
        wsplit_kernel<<<dim3(64, 32), 256>>>(Wg + (size_t)l * D * FF, whi + B0 + 12 * OW, wlo + B0 + 12 * OW, 2048, 1024);
        wsplit_kernel<<<dim3(64, 32), 256>>>(Wu + (size_t)l * D * FF, whi + B0 + 14 * OW, wlo + B0 + 14 * OW, 2048, 1024);
        wsplit_kernel<<<dim3(32, 64), 256>>>(Wd + (size_t)l * FF * D, whi + B0 + 16 * OW, wlo + B0 + 16 * OW, 1024, 2048);
    }

    for (int l = 0; l < 8; l++) {
        blend_kernel<<<128, 256>>>(cat, memory + (size_t)l * MD, out + (size_t)l * MD);
        if (l == 7) break;

        size_t B0 = (size_t)l * WLAYER;

        rms_kernel<<<1280, 256>>>(cat, ln1 + (size_t)l * D, xhi, xlo);
        memcvt_kernel<<<128, 256>>>(memory + (size_t)l * MD, mhi, mlo);

        TGB bb;
        bb.g[0].ahi = xhi; bb.g[0].alo = xlo; bb.g[0].whi = whi + B0 + 0 * OW; bb.g[0].wlo = wlo + B0 + 0 * OW; bb.g[0].c = q;
        bb.g[1].ahi = xhi; bb.g[1].alo = xlo; bb.g[1].whi = whi + B0 + 1 * OW; bb.g[1].wlo = wlo + B0 + 1 * OW; bb.g[1].c = k + 128 * D;
        bb.g[2].ahi = xhi; bb.g[2].alo = xlo; bb.g[2].whi = whi + B0 + 2 * OW; bb.g[2].wlo = wlo + B0 + 2 * OW; bb.g[2].c = v + 128 * D;
        tcgemm_kernel<<<dim3(8, 8, 3), 256, SMSZ>>>(bb, 1024, 1024, 0);

        const __nv_bfloat16* xbh = xhi + (size_t)1024 * D;
        const __nv_bfloat16* xbl = xlo + (size_t)1024 * D;
        const __nv_bfloat16* xfh = xhi + (size_t)1152 * D;
        const __nv_bfloat16* xfl = xlo + (size_t)1152 * D;
        TGB sb2;
        sb2.g[0].ahi = mhi; sb2.g[0].alo = mlo; sb2.g[0].whi = whi + B0 + 4 * OW;  sb2.g[0].wlo = wlo + B0 + 4 * OW;  sb2.g[0].c = k;
        sb2.g[1].ahi = mhi; sb2.g[1].alo = mlo; sb2.g[1].whi = whi + B0 + 5 * OW;  sb2.g[1].wlo = wlo + B0 + 5 * OW;  sb2.g[1].c = v;
        sb2.g[2].ahi = xbh; sb2.g[2].alo = xbl; sb2.g[2].whi = whi + B0 + 6 * OW;  sb2.g[2].wlo = wlo + B0 + 6 * OW;  sb2.g[2].c = q + 1024 * D;
        sb2.g[3].ahi = xbh; sb2.g[3].alo = xbl; sb2.g[3].whi = whi + B0 + 7 * OW;  sb2.g[3].wlo = wlo + B0 + 7 * OW;  sb2.g[3].c = k + 1152 * D;
        sb2.g[4].ahi = xbh; sb2.g[4].alo = xbl; sb2.g[4].whi = whi + B0 + 8 * OW;  sb2.g[4].wlo = wlo + B0 + 8 * OW;  sb2.g[4].c = v + 1152 * D;
        sb2.g[5].ahi = xfh; sb2.g[5].alo = xfl; sb2.g[5].whi = whi + B0 + 9 * OW;  sb2.g[5].wlo = wlo + B0 + 9 * OW;  sb2.g[5].c = q + 1152 * D;
        sb2.g[6].ahi = xfh; sb2.g[6].alo = xfl; sb2.g[6].whi = whi + B0 + 10 * OW; sb2.g[6].wlo = wlo + B0 + 10 * OW; sb2.g[6].c = k + 1280 * D;
        sb2.g[7].ahi = xfh; sb2.g[7].alo = xfl; sb2.g[7].whi = whi + B0 + 11 * OW; sb2.g[7].wlo = wlo + B0 + 11 * OW; sb2.g[7].c = v + 1280 * D;
        tcgemm_kernel<<<dim3(8, 1, 8), 256, SMSZ>>>(sb2, 1024, 1024, 0);

        rope_kernel<<<2688, 512>>>(q, k, cs, sn);

        AA aa;
        aa.K1 = k; aa.V1 = v;
        aa.d[0].Q = q;            aa.d[0].K2 = 0;            aa.d[0].V2 = 0;            aa.d[0].Ohi = athi;            aa.d[0].Olo = atlo;            aa.d[0].nq = 1024; aa.d[0].off = 128;
        aa.d[1].Q = q + 1024 * D; aa.d[1].K2 = k + 1152 * D; aa.d[1].V2 = v + 1152 * D; aa.d[1].Ohi = athi + 1024 * D; aa.d[1].Olo = atlo + 1024 * D; aa.d[1].nq = 128;  aa.d[1].off = 1152;
        aa.d[2].Q = q + 1152 * D; aa.d[2].K2 = k + 1280 * D; aa.d[2].V2 = v + 1280 * D; aa.d[2].Ohi = athi + 1152 * D; aa.d[2].Olo = atlo + 1152 * D; aa.d[2].nq = 128;  aa.d[2].off = 1152;
        attn_kernel<<<dim3(16, 16, 3), 256>>>(aa);

        TGB ob;
        ob.g[0].ahi = athi; ob.g[0].alo = atlo; ob.g[0].whi = whi + B0 + 3 * OW; ob.g[0].wlo = wlo + B0 + 3 * OW; ob.g[0].c = cat;
        tcgemm_kernel<<<dim3(8, 10, 1), 256, SMSZ>>>(ob, 1024, 1024, 1);

        rms_kernel<<<1280, 256>>>(cat, ln2 + (size_t)l * D, xhi, xlo);

        TGB mb;
        mb.g[0].ahi = xhi; mb.g[0].alo = xlo; mb.g[0].whi = whi + B0 + 12 * OW; mb.g[0].wlo = wlo + B0 + 12 * OW; mb.g[0].c = t1;
        mb.g[1].ahi = xhi; mb.g[1].alo = xlo; mb.g[1].whi = whi + B0 + 14 * OW; mb.g[1].wlo = wlo + B0 + 14 * OW; mb.g[1].c = t2;
        tcgemm_kernel<<<dim3(16, 10, 2), 256, SMSZ>>>(mb, 2048, 1024, 0);

        silu_kernel<<<CATR * FF / 1024, 256>>>(t1, t2, t1hi, t1lo);

        TGB db;
        db.g[0].ahi = t1hi; db.g[0].alo = t1lo; db.g[0].whi = whi + B0 + 16 * OW; db.g[0].wlo = wlo + B0 + 16 * OW; db.g[0].c = cat;
        tcgemm_kernel<<<dim3(8, 10, 1), 256, SMSZ>>>(db, 1024, 2048, 1);
    }
}

// round 12
// speedup vs baseline: 1.4804x; 1.0702x over previous
#include <cuda_runtime.h>
#include <cuda_bf16.h>
#include <cstdint>
#include <math.h>

typedef unsigned int u32;
typedef unsigned long long u64;

#define D    1024
#define HDIM 64
#define FF   2048
#define CATR 1280
#define KR   1408
#define SPLITK 1152

// ---------------- scratch (device globals) ----------------
__device__ float g_cat[CATR * D];
__device__ __nv_bfloat16 g_xhi[CATR * D];
__device__ __nv_bfloat16 g_xlo[CATR * D];
__device__ float g_q[CATR * D];
__device__ float g_k[KR * D];
__device__ float g_v[KR * D];
__device__ __nv_bfloat16 g_athi[CATR * D];
__device__ __nv_bfloat16 g_atlo[CATR * D];
__device__ float g_t1[CATR * FF];
__device__ float g_t2[CATR * FF];
__device__ __nv_bfloat16 g_t1hi[CATR * FF];
__device__ __nv_bfloat16 g_t1lo[CATR * FF];
__device__ __nv_bfloat16 g_mhi[128 * D];
__device__ __nv_bfloat16 g_mlo[128 * D];
__device__ float g_cosT[1280 * 32];
__device__ float g_sinT[1280 * 32];
#define WLAYER 18874368ull
__device__ __nv_bfloat16 g_whi[7 * WLAYER];
__device__ __nv_bfloat16 g_wlo[7 * WLAYER];

// ---------------- helpers ----------------
__device__ __forceinline__ u32 smem_u32(const void* p) {
    u32 a;
    asm("{ .reg .u64 t; cvta.to.shared.u64 t, %1; cvt.u32.u64 %0, t; }" : "=r"(a) : "l"(p));
    return a;
}

__device__ __forceinline__ void ldsm4(u32* r, u32 addr) {
    asm volatile("ldmatrix.sync.aligned.m8n8.x4.shared.b16 {%0, %1, %2, %3}, [%4];"
        : "=r"(r[0]), "=r"(r[1]), "=r"(r[2]), "=r"(r[3]) : "r"(addr));
}

__device__ __forceinline__ void mma_bf16(float* c, const u32* a, const u32* b) {
    asm volatile("mma.sync.aligned.m16n8k16.row.col.f32.bf16.bf16.f32 "
        "{%0, %1, %2, %3}, {%4, %5, %6, %7}, {%8, %9}, {%0, %1, %2, %3};"
        : "+f"(c[0]), "+f"(c[1]), "+f"(c[2]), "+f"(c[3])
        : "r"(a[0]), "r"(a[1]), "r"(a[2]), "r"(a[3]), "r"(b[0]), "r"(b[1]));
}

__device__ __forceinline__ void cp16(u32 dst, const void* src) {
    asm volatile("cp.async.cg.shared.global [%0], [%1], 16;" :: "r"(dst), "l"(src));
}
#define CP_COMMIT() asm volatile("cp.async.commit_group;" ::: "memory")
#define CP_WAIT2()  asm volatile("cp.async.wait_group 2;" ::: "memory")

__device__ __forceinline__ void split_store(__nv_bfloat16* hi, __nv_bfloat16* lo, size_t i, float v) {
    __nv_bfloat16 h = __float2bfloat16(v);
    hi[i] = h;
    lo[i] = __float2bfloat16(v - __bfloat162float(h));
}

// ---------------- small kernels ----------------
__global__ void rope_setup_kernel(float* cs, float* sn) {
    int pos = blockIdx.x;
    int i = threadIdx.x;
    double inv = 1.0 / pow(10000.0, (double)(2 * i) / 64.0);
    double ang = (double)pos * inv;
    cs[pos * 32 + i] = (float)cos(ang);
    sn[pos * 32 + i] = (float)sin(ang);
}

__global__ void __launch_bounds__(256) embed_kernel(const int* __restrict__ ids,
        const float* __restrict__ emb, const float* __restrict__ bcn,
        const float* __restrict__ fgt, float* __restrict__ cat) {
    int r = blockIdx.x;
    int t = threadIdx.x;
    const float* src;
    if (r < 1024)      src = emb + (size_t)ids[r] * D;
    else if (r < 1152) src = bcn + (size_t)(r - 1024) * D;
    else               src = fgt + (size_t)(r - 1152) * D;
    *(float4*)(cat + (size_t)r * D + t * 4) = *(const float4*)(src + t * 4);
}

__global__ void __launch_bounds__(256) blend_kernel(const float* __restrict__ cat,
        const float* __restrict__ mem, float* __restrict__ out) {
    int m = blockIdx.x;
    int c = threadIdx.x * 4;
    float4 fg = *(const float4*)(cat + (size_t)(1152 + m) * D + c);
    float4 bc = *(const float4*)(cat + (size_t)(1024 + m) * D + c);
    float4 mv = *(const float4*)(mem + (size_t)m * D + c);
    float4 o;
    float g;
    g = 1.0f / (1.0f + expf(-fg.x)); o.x = mv.x * g + bc.x * (1.0f - g);
    g = 1.0f / (1.0f + expf(-fg.y)); o.y = mv.y * g + bc.y * (1.0f - g);
    g = 1.0f / (1.0f + expf(-fg.z)); o.z = mv.z * g + bc.z * (1.0f - g);
    g = 1.0f / (1.0f + expf(-fg.w)); o.w = mv.w * g + bc.w * (1.0f - g);
    *(float4*)(out + (size_t)m * D + c) = o;
}

__global__ void __launch_bounds__(256) rms_kernel(const float* __restrict__ in,
        const float* __restrict__ w, __nv_bfloat16* __restrict__ xhi, __nv_bfloat16* __restrict__ xlo) {
    int row = blockIdx.x;
    int t = threadIdx.x;
    float4 v = *(const float4*)(in + (size_t)row * D + t * 4);
    float ss = v.x * v.x + v.y * v.y + v.z * v.z + v.w * v.w;
    #pragma unroll
    for (int o = 16; o > 0; o >>= 1) ss += __shfl_xor_sync(0xffffffffu, ss, o);
    __shared__ float sred[8];
    __shared__ float stot;
    if ((t & 31) == 0) sred[t >> 5] = ss;
    __syncthreads();
    if (t == 0) {
        float z = 0.0f;
        for (int i = 0; i < 8; i++) z += sred[i];
        stot = z;
    }
    __syncthreads();
    float r = rsqrtf(stot * (1.0f / 1024.0f) + 1e-5f);
    float4 wv = *(const float4*)(w + t * 4);
    size_t base = (size_t)row * D + t * 4;
    split_store(xhi, xlo, base + 0, v.x * wv.x * r);
    split_store(xhi, xlo, base + 1, v.y * wv.y * r);
    split_store(xhi, xlo, base + 2, v.z * wv.z * r);
    split_store(xhi, xlo, base + 3, v.w * wv.w * r);
}

__global__ void __launch_bounds__(256) memcvt_kernel(const float* __restrict__ mem,
        __nv_bfloat16* __restrict__ hi, __nv_bfloat16* __restrict__ lo) {
    int r = blockIdx.x;
    int t = threadIdx.x;
    size_t base = (size_t)r * D + t * 4;
    #pragma unroll
    for (int i = 0; i < 4; i++) split_store(hi, lo, base + i, mem[base + i]);
}

// ---------------- batched weight transpose+split (all layers, one launch) ----------------
#define TPL 18432
struct WS { const float* w[12]; const float* wg; const float* wu; const float* wd;
            __nv_bfloat16* whi; __nv_bfloat16* wlo; };

__global__ void __launch_bounds__(256) wsplit_all_kernel(WS ws) {
    int blk = blockIdx.x;
    int l = blk / TPL;
    int w = blk % TPL;
    const float* src;
    __nv_bfloat16* hi;
    __nv_bfloat16* lo;
    int N, K, n0, k0;
    size_t B0 = (size_t)l * WLAYER;
    const size_t OW = 1048576;
    if (w < 12288) {
        int wi = w >> 10;
        int t2 = w & 1023;
        n0 = (t2 & 31) * 32; k0 = (t2 >> 5) * 32;
        N = 1024; K = 1024;
        src = ws.w[wi] + (size_t)l * D * D;
        hi = ws.whi + B0 + (size_t)wi * OW;
        lo = ws.wlo + B0 + (size_t)wi * OW;
    } else if (w < 14336) {
        int t2 = w - 12288;
        n0 = (t2 & 63) * 32; k0 = (t2 >> 6) * 32;
        N = 2048; K = 1024;
        src = ws.wg + (size_t)l * D * FF;
        hi = ws.whi + B0 + 12 * OW;
        lo = ws.wlo + B0 + 12 * OW;
    } else if (w < 16384) {
        int t2 = w - 14336;
        n0 = (t2 & 63) * 32; k0 = (t2 >> 6) * 32;
        N = 2048; K = 1024;
        src = ws.wu + (size_t)l * D * FF;
        hi = ws.whi + B0 + 14 * OW;
        lo = ws.wlo + B0 + 14 * OW;
    } else {
        int t2 = w - 16384;
        n0 = (t2 & 31) * 32; k0 = (t2 >> 5) * 32;
        N = 1024; K = 2048;
        src = ws.wd + (size_t)l * FF * D;
        hi = ws.whi + B0 + 16 * OW;
        lo = ws.wlo + B0 + 16 * OW;
    }
    __shared__ float tile[32][33];
    int tx = threadIdx.x & 31;
    int ty = threadIdx.x >> 5;
    #pragma unroll
    for (int j = 0; j < 4; j++)
        tile[ty + 8 * j][tx] = src[(size_t)(k0 + ty + 8 * j) * N + n0 + tx];
    __syncthreads();
    #pragma unroll
    for (int j = 0; j < 4; j++) {
        int nr = ty + 8 * j;
        split_store(hi, lo, (size_t)(n0 + nr) * K + k0 + tx, tile[tx][nr]);
    }
}

// ---------------- mma.sync GEMM v2: 64x128 tile, cp.async 3-stage, 2 CTA/SM ----------------
struct TGD { const __nv_bfloat16* ahi; const __nv_bfloat16* alo;
             const __nv_bfloat16* whi; const __nv_bfloat16* wlo; float* c; int rows; };
struct TGB { TGD g[12]; };

#define STG_BUF 30720
#define PITCH   80

__global__ void __launch_bounds__(256, 2) tcgemm_kernel(TGB b, int N, int K, int acc) {
    TGD dd = b.g[blockIdx.z];
    int m0 = blockIdx.y * 64;
    if (m0 >= dd.rows) return;
    int n0 = blockIdx.x * 128;
    extern __shared__ __align__(16) char smem[];
    u32 smb = smem_u32(smem);

    int t = threadIdx.x;
    int lane = t & 31;
    int wid = t >> 5;
    int wm = (wid >> 2) * 32;
    int wn = (wid & 3) * 32;

    const char* srcb[6];
    u32 dsto[6];
    {
        int r4 = t >> 2, c4 = t & 3;
        srcb[0] = (const char*)(dd.ahi + (size_t)(m0 + r4) * K + c4 * 8);
        dsto[0] = (u32)(r4 * PITCH + c4 * 16);
        srcb[1] = (const char*)(dd.alo + (size_t)(m0 + r4) * K + c4 * 8);
        dsto[1] = dsto[0] + 5120;
        srcb[2] = (const char*)(dd.whi + (size_t)(n0 + r4) * K + c4 * 8);
        dsto[2] = (u32)(10240 + r4 * PITCH + c4 * 16);
        srcb[3] = (const char*)(dd.whi + (size_t)(n0 + 64 + r4) * K + c4 * 8);
        dsto[3] = (u32)(10240 + (64 + r4) * PITCH + c4 * 16);
        srcb[4] = (const char*)(dd.wlo + (size_t)(n0 + r4) * K + c4 * 8);
        dsto[4] = dsto[2] + 10240;
        srcb[5] = (const char*)(dd.wlo + (size_t)(n0 + 64 + r4) * K + c4 * 8);
        dsto[5] = dsto[3] + 10240;
    }

    float accf[2][4][4];
    #pragma unroll
    for (int mt = 0; mt < 2; mt++)
        #pragma unroll
        for (int nt = 0; nt < 4; nt++)
            #pragma unroll
            for (int i = 0; i < 4; i++) accf[mt][nt][i] = 0.0f;

    int nch = K / 32;

    #pragma unroll
    for (int s = 0; s < 3; s++) {
        u32 db = smb + s * STG_BUF;
        #pragma unroll
        for (int j = 0; j < 6; j++) cp16(db + dsto[j], srcb[j] + (size_t)s * 64);
        CP_COMMIT();
    }

    u32 lrow = (u32)(lane & 15);
    u32 lc16 = (u32)((lane >> 4) * 16);

    int stage = 0;
    for (int c = 0; c < nch; c++) {
        CP_WAIT2();
        __syncthreads();
        u32 bufb = smb + stage * STG_BUF;
        #pragma unroll
        for (int ks = 0; ks < 2; ks++) {
            u32 kb = (u32)(ks * 32);
            u32 ah[2][4], al[2][4], bh[4][2], bl[4][2];
            #pragma unroll
            for (int mt = 0; mt < 2; mt++) {
                u32 addr = bufb + (wm + mt * 16 + lrow) * PITCH + kb + lc16;
                ldsm4(ah[mt], addr);
                ldsm4(al[mt], addr + 5120);
            }
            #pragma unroll
            for (int p = 0; p < 2; p++) {
                u32 raw[4];
                u32 addr = bufb + 10240 + (wn + p * 16 + lrow) * PITCH + kb + lc16;
                ldsm4(raw, addr);
                bh[p * 2][0] = raw[0]; bh[p * 2][1] = raw[2];
                bh[p * 2 + 1][0] = raw[1]; bh[p * 2 + 1][1] = raw[3];
                ldsm4(raw, addr + 10240);
                bl[p * 2][0] = raw[0]; bl[p * 2][1] = raw[2];
                bl[p * 2 + 1][0] = raw[1]; bl[p * 2 + 1][1] = raw[3];
            }
            #pragma unroll
            for (int mt = 0; mt < 2; mt++) {
                #pragma unroll
                for (int nt = 0; nt < 4; nt++) {
                    mma_bf16(accf[mt][nt], ah[mt], bh[nt]);
                    mma_bf16(accf[mt][nt], ah[mt], bl[nt]);
                    mma_bf16(accf[mt][nt], al[mt], bh[nt]);
                }
            }
        }
        __syncthreads();
        if (c + 3 < nch) {
            u32 db = smb + stage * STG_BUF;
            #pragma unroll
            for (int j = 0; j < 6; j++) cp16(db + dsto[j], srcb[j] + (size_t)(c + 3) * 64);
        }
        CP_COMMIT();
        stage = (stage + 1 == 3) ? 0 : stage + 1;
    }

    int r0 = lane >> 2;
    int c0 = (lane & 3) * 2;
    #pragma unroll
    for (int mt = 0; mt < 2; mt++) {
        #pragma unroll
        for (int nt = 0; nt < 4; nt++) {
            int row = m0 + wm + mt * 16 + r0;
            int col = n0 + wn + nt * 8 + c0;
            float* p0 = dd.c + (size_t)row * N + col;
            float* p1 = dd.c + (size_t)(row + 8) * N + col;
            float2 v0, v1;
            v0.x = accf[mt][nt][0]; v0.y = accf[mt][nt][1];
            v1.x = accf[mt][nt][2]; v1.y = accf[mt][nt][3];
            if (acc) {
                float2 o0 = *(const float2*)p0;
                float2 o1 = *(const float2*)p1;
                v0.x += o0.x; v0.y += o0.y;
                v1.x += o1.x; v1.y += o1.y;
            }
            *(float2*)p0 = v0;
            *(float2*)p1 = v1;
        }
    }
}

// ---------------- rope ----------------
__global__ void __launch_bounds__(512) rope_kernel(float* q, float* k,
        const float* __restrict__ cs, const float* __restrict__ sn) {
    int idx = blockIdx.x;
    float* buf;
    int r, pos;
    if (idx < 1280) { buf = q; r = idx; pos = (r < 1152) ? r + 128 : r; }
    else            { buf = k; r = idx - 1280; pos = (r < 1280) ? r : r - 128; }
    int t = threadIdx.x;
    int h = t >> 5;
    int j = t & 31;
    float* p = buf + (size_t)r * D + h * HDIM;
    float x0 = p[j];
    float x1 = p[j + 32];
    float c = cs[pos * 32 + j];
    float s = sn[pos * 32 + j];
    p[j] = x0 * c - x1 * s;
    p[j + 32] = x1 * c + x0 * s;
}

// ---------------- fused flash attention ----------------
struct AD { const float* Q; const float* K2; const float* V2;
            __nv_bfloat16* Ohi; __nv_bfloat16* Olo; int nq; int off; };
struct AA { const float* K1; const float* V1; AD d[3]; };

__global__ void __launch_bounds__(256) attn_kernel(AA args) {
    AD ad = args.d[blockIdx.z];
    int q0 = blockIdx.x * 64;
    if (q0 >= ad.nq) return;
    int h = blockIdx.y;
    __shared__ __align__(16) float Qs[64][68];
    __shared__ __align__(16) float Ks[32][68];
    __shared__ __align__(16) float Vs[32][68];
    __shared__ __align__(16) float Ps[64][36];
    int t = threadIdx.x;
    {
        int col = (t & 15) * 4;
        int rb = t >> 4;
        #pragma unroll
        for (int rr = 0; rr < 4; rr++) {
            int row = rb + rr * 16;
            float4 v = *(const float4*)(ad.Q + (size_t)(q0 + row) * D + h * HDIM + col);
            v.x *= 0.125f; v.y *= 0.125f; v.z *= 0.125f; v.w *= 0.125f;
            *(float4*)&Qs[row][col] = v;
        }
    }
    int qy = t >> 2;
    int kq = t & 3;
    int qi = q0 + qy;
    float O[16];
    #pragma unroll
    for (int i = 0; i < 16; i++) O[i] = 0.0f;
    float mM = -1e30f, lS = 0.0f;
    int nk = ad.off + ad.nq;
    int jmax = min(nk, q0 + 64 + ad.off);
    for (int j0 = 0; j0 < jmax; j0 += 32) {
        __syncthreads();
        {
            int jr = t >> 3;
            int cc = (t & 7) * 8;
            int j = j0 + jr;
            if (j < nk) {
                const float* kp = (j < SPLITK) ? (args.K1 + (size_t)j * D) : (ad.K2 + (size_t)(j - SPLITK) * D);
                const float* vp = (j < SPLITK) ? (args.V1 + (size_t)j * D) : (ad.V2 + (size_t)(j - SPLITK) * D);
                *(float4*)&Ks[jr][cc]     = *(const float4*)(kp + h * HDIM + cc);
                *(float4*)&Ks[jr][cc + 4] = *(const float4*)(kp + h * HDIM + cc + 4);
                *(float4*)&Vs[jr][cc]     = *(const float4*)(vp + h * HDIM + cc);
                *(float4*)&Vs[jr][cc + 4] = *(const float4*)(vp + h * HDIM + cc + 4);
            } else {
                float4 z = make_float4(0.0f, 0.0f, 0.0f, 0.0f);
                *(float4*)&Ks[jr][cc] = z;
                *(float4*)&Ks[jr][cc + 4] = z;
                *(float4*)&Vs[jr][cc] = z;
                *(float4*)&Vs[jr][cc + 4] = z;
            }
        }
        __syncthreads();
        float s[8];
        #pragma unroll
        for (int jj = 0; jj < 8; jj++) s[jj] = 0.0f;
        #pragma unroll
        for (int d4 = 0; d4 < 16; d4++) {
            float4 qv = *(const float4*)&Qs[qy][d4 * 4];
            #pragma unroll
            for (int jj = 0; jj < 8; jj++) {
                float4 kv = *(const float4*)&Ks[kq * 8 + jj][d4 * 4];
                s[jj] += qv.x * kv.x + qv.y * kv.y + qv.z * kv.z + qv.w * kv.w;
            }
        }
        #pragma unroll
        for (int jj = 0; jj < 8; jj++) {
            int j = j0 + kq * 8 + jj;
            if (j > qi + ad.off) s[jj] = -1e30f;
        }
        float tmax = s[0];
        #pragma unroll
        for (int jj = 1; jj < 8; jj++) tmax = fmaxf(tmax, s[jj]);
        tmax = fmaxf(tmax, __shfl_xor_sync(0xffffffffu, tmax, 1));
        tmax = fmaxf(tmax, __shfl_xor_sync(0xffffffffu, tmax, 2));
        float mn = fmaxf(mM, tmax);
        float p[8], ps = 0.0f;
        #pragma unroll
        for (int jj = 0; jj < 8; jj++) { p[jj] = __expf(s[jj] - mn); ps += p[jj]; }
        ps += __shfl_xor_sync(0xffffffffu, ps, 1);
        ps += __shfl_xor_sync(0xffffffffu, ps, 2);
        float alpha = __expf(mM - mn);
        lS = lS * alpha + ps;
        mM = mn;
        #pragma unroll
        for (int i = 0; i < 16; i++) O[i] *= alpha;
        #pragma unroll
        for (int jj = 0; jj < 8; jj++) Ps[qy][kq * 8 + jj] = p[jj];
        __syncthreads();
        #pragma unroll 8
        for (int j = 0; j < 32; j++) {
            float pv = Ps[qy][j];
            float4 v0 = *(const float4*)&Vs[j][kq * 16];
            float4 v1 = *(const float4*)&Vs[j][kq * 16 + 4];
            float4 v2 = *(const float4*)&Vs[j][kq * 16 + 8];
            float4 v3 = *(const float4*)&Vs[j][kq * 16 + 12];
            O[0]  += pv * v0.x; O[1]  += pv * v0.y; O[2]  += pv * v0.z; O[3]  += pv * v0.w;
            O[4]  += pv * v1.x; O[5]  += pv * v1.y; O[6]  += pv * v1.z; O[7]  += pv * v1.w;
            O[8]  += pv * v2.x; O[9]  += pv * v2.y; O[10] += pv * v2.z; O[11] += pv * v2.w;
            O[12] += pv * v3.x; O[13] += pv * v3.y; O[14] += pv * v3.z; O[15] += pv * v3.w;
        }
    }
    float inv = 1.0f / lS;
    size_t base = (size_t)qi * D + h * HDIM + kq * 16;
    #pragma unroll
    for (int i = 0; i < 16; i++) split_store(ad.Ohi, ad.Olo, base + i, O[i] * inv);
}

__global__ void __launch_bounds__(256) silu_kernel(const float* __restrict__ t1,
        const float* __restrict__ t2, __nv_bfloat16* __restrict__ hi, __nv_bfloat16* __restrict__ lo) {
    size_t i = ((size_t)blockIdx.x * 256 + threadIdx.x) * 4;
    float4 a = *(const float4*)(t1 + i);
    float4 b = *(const float4*)(t2 + i);
    split_store(hi, lo, i + 0, (a.x / (1.0f + expf(-a.x))) * b.x);
    split_store(hi, lo, i + 1, (a.y / (1.0f + expf(-a.y))) * b.y);
    split_store(hi, lo, i + 2, (a.z / (1.0f + expf(-a.z))) * b.z);
    split_store(hi, lo, i + 3, (a.w / (1.0f + expf(-a.w))) * b.w);
}

// ---------------- host ----------------
extern "C" void kernel_launch(void* const* d_in, const int* in_sizes, int n_in,
                              void* d_out, int out_size) {
    const int*   ids    = (const int*)  d_in[0];
    const float* memory = (const float*)d_in[1];
    const float* beacon = (const float*)d_in[2];
    const float* forget = (const float*)d_in[3];
    const float* embedW = (const float*)d_in[4];
    const float* ln1    = (const float*)d_in[5];
    const float* ln2    = (const float*)d_in[6];
    const float* Wg = (const float*)d_in[19];
    const float* Wu = (const float*)d_in[20];
    const float* Wd = (const float*)d_in[21];
    float* out = (float*)d_out;

    float *cat, *q, *k, *v, *t1, *t2, *cs, *sn;
    __nv_bfloat16 *xhi, *xlo, *athi, *atlo, *t1hi, *t1lo, *mhi, *mlo, *whi, *wlo;
    cudaGetSymbolAddress((void**)&cat,  g_cat);
    cudaGetSymbolAddress((void**)&xhi,  g_xhi);
    cudaGetSymbolAddress((void**)&xlo,  g_xlo);
    cudaGetSymbolAddress((void**)&q,    g_q);
    cudaGetSymbolAddress((void**)&k,    g_k);
    cudaGetSymbolAddress((void**)&v,    g_v);
    cudaGetSymbolAddress((void**)&athi, g_athi);
    cudaGetSymbolAddress((void**)&atlo, g_atlo);
    cudaGetSymbolAddress((void**)&t1,   g_t1);
    cudaGetSymbolAddress((void**)&t2,   g_t2);
    cudaGetSymbolAddress((void**)&t1hi, g_t1hi);
    cudaGetSymbolAddress((void**)&t1lo, g_t1lo);
    cudaGetSymbolAddress((void**)&mhi,  g_mhi);
    cudaGetSymbolAddress((void**)&mlo,  g_mlo);
    cudaGetSymbolAddress((void**)&whi,  g_whi);
    cudaGetSymbolAddress((void**)&wlo,  g_wlo);
    cudaGetSymbolAddress((void**)&cs,   g_cosT);
    cudaGetSymbolAddress((void**)&sn,   g_sinT);

    cudaFuncSetAttribute(tcgemm_kernel, cudaFuncAttributeMaxDynamicSharedMemorySize, 3 * STG_BUF);

    const size_t MD = (size_t)128 * D;
    const size_t OW = 1048576;
    const int SMSZ = 3 * STG_BUF;

    rope_setup_kernel<<<1280, 32>>>(cs, sn);
    embed_kernel<<<1280, 256>>>(ids, embedW, beacon, forget, cat);

    WS ws;
    for (int wi = 0; wi < 12; wi++) ws.w[wi] = (const float*)d_in[7 + wi];
    ws.wg = Wg; ws.wu = Wu; ws.wd = Wd;
    ws.whi = whi; ws.wlo = wlo;
    wsplit_all_kernel<<<7 * TPL, 256>>>(ws);

    for (int l = 0; l < 8; l++) {
        blend_kernel<<<128, 256>>>(cat, memory + (size_t)l * MD, out + (size_t)l * MD);
        if (l == 7) break;

        size_t B0 = (size_t)l * WLAYER;

        rms_kernel<<<1280, 256>>>(cat, ln1 + (size_t)l * D, xhi, xlo);
        memcvt_kernel<<<128, 256>>>(memory + (size_t)l * MD, mhi, mlo);

        const __nv_bfloat16* xbh = xhi + (size_t)1024 * D;
        const __nv_bfloat16* xbl = xlo + (size_t)1024 * D;
        const __nv_bfloat16* xfh = xhi + (size_t)1152 * D;
        const __nv_bfloat16* xfl = xlo + (size_t)1152 * D;

        TGB bb;
        bb.g[0].ahi = xhi; bb.g[0].alo = xlo; bb.g[0].whi = whi + B0 + 0 * OW; bb.g[0].wlo = wlo + B0 + 0 * OW; bb.g[0].c = q;            bb.g[0].rows = 1024;
        bb.g[1].ahi = xhi; bb.g[1].alo = xlo; bb.g[1].whi = whi + B0 + 1 * OW; bb.g[1].wlo = wlo + B0 + 1 * OW; bb.g[1].c = k + 128 * D;  bb.g[1].rows = 1024;
        bb.g[2].ahi = xhi; bb.g[2].alo = xlo; bb.g[2].whi = whi + B0 + 2 * OW; bb.g[2].wlo = wlo + B0 + 2 * OW; bb.g[2].c = v + 128 * D;  bb.g[2].rows = 1024;
        bb.g[3].ahi = mhi; bb.g[3].alo = mlo; bb.g[3].whi = whi + B0 + 4 * OW;  bb.g[3].wlo = wlo + B0 + 4 * OW;  bb.g[3].c = k;             bb.g[3].rows = 128;
        bb.g[4].ahi = mhi; bb.g[4].alo = mlo; bb.g[4].whi = whi + B0 + 5 * OW;  bb.g[4].wlo = wlo + B0 + 5 * OW;  bb.g[4].c = v;             bb.g[4].rows = 128;
        bb.g[5].ahi = xbh; bb.g[5].alo = xbl; bb.g[5].whi = whi + B0 + 6 * OW;  bb.g[5].wlo = wlo + B0 + 6 * OW;  bb.g[5].c = q + 1024 * D;  bb.g[5].rows = 128;
        bb.g[6].ahi = xbh; bb.g[6].alo = xbl; bb.g[6].whi = whi + B0 + 7 * OW;  bb.g[6].wlo = wlo + B0 + 7 * OW;  bb.g[6].c = k + 1152 * D;  bb.g[6].rows = 128;
        bb.g[7].ahi = xbh; bb.g[7].alo = xbl; bb.g[7].whi = whi + B0 + 8 * OW;  bb.g[7].wlo = wlo + B0 + 8 * OW;  bb.g[7].c = v + 1152 * D;  bb.g[7].rows = 128;
        bb.g[8].ahi = xfh; bb.g[8].alo = xfl; bb.g[8].whi = whi + B0 + 9 * OW;  bb.g[8].wlo = wlo + B0 + 9 * OW;  bb.g[8].c = q + 1152 * D;  bb.g[8].rows = 128;
        bb.g[9].ahi = xfh; bb.g[9].alo = xfl; bb.g[9].whi = whi + B0 + 10 * OW; bb.g[9].wlo = wlo + B0 + 10 * OW; bb.g[9].c = k + 1280 * D;  bb.g[9].rows = 128;
        bb.g[10].ahi = xfh; bb.g[10].alo = xfl; bb.g[10].whi = whi + B0 + 11 * OW; bb.g[10].wlo = wlo + B0 + 11 * OW; bb.g[10].c = v + 1280 * D; bb.g[10].rows = 128;
        tcgemm_kernel<<<dim3(8, 16, 11), 256, SMSZ>>>(bb, 1024, 1024, 0);

        rope_kernel<<<2688, 512>>>(q, k, cs, sn);

        AA aa;
        aa.K1 = k; aa.V1 = v;
        aa.d[0].Q = q;            aa.d[0].K2 = 0;            aa.d[0].V2 = 0;            aa.d[0].Ohi = athi;            aa.d[0].Olo = atlo;            aa.d[0].nq = 1024; aa.d[0].off = 128;
        aa.d[1].Q = q + 1024 * D; aa.d[1].K2 = k + 1152 * D; aa.d[1].V2 = v + 1152 * D; aa.d[1].Ohi = athi + 1024 * D; aa.d[1].Olo = atlo + 1024 * D; aa.d[1].nq = 128;  aa.d[1].off = 1152;
        aa.d[2].Q = q + 1152 * D; aa.d[2].K2 = k + 1280 * D; aa.d[2].V2 = v + 1280 * D; aa.d[2].Ohi = athi + 1152 * D; aa.d[2].Olo = atlo + 1152 * D; aa.d[2].nq = 128;  aa.d[2].off = 1152;
        attn_kernel<<<dim3(16, 16, 3), 256>>>(aa);

        TGB ob;
        ob.g[0].ahi = athi; ob.g[0].alo = atlo; ob.g[0].whi = whi + B0 + 3 * OW; ob.g[0].wlo = wlo + B0 + 3 * OW; ob.g[0].c = cat; ob.g[0].rows = 1280;
        tcgemm_kernel<<<dim3(8, 20, 1), 256, SMSZ>>>(ob, 1024, 1024, 1);

        rms_kernel<<<1280, 256>>>(cat, ln2 + (size_t)l * D, xhi, xlo);

        TGB mb;
        mb.g[0].ahi = xhi; mb.g[0].alo = xlo; mb.g[0].whi = whi + B0 + 12 * OW; mb.g[0].wlo = wlo + B0 + 12 * OW; mb.g[0].c = t1; mb.g[0].rows = 1280;
        mb.g[1].ahi = xhi; mb.g[1].alo = xlo; mb.g[1].whi = whi + B0 + 14 * OW; mb.g[1].wlo = wlo + B0 + 14 * OW; mb.g[1].c = t2; mb.g[1].rows = 1280;
        tcgemm_kernel<<<dim3(16, 20, 2), 256, SMSZ>>>(mb, 2048, 1024, 0);

        silu_kernel<<<CATR * FF / 1024, 256>>>(t1, t2, t1hi, t1lo);

        TGB db;
        db.g[0].ahi = t1hi; db.g[0].alo = t1lo; db.g[0].whi = whi + B0 + 16 * OW; db.g[0].wlo = wlo + B0 + 16 * OW; db.g[0].c = cat; db.g[0].rows = 1280;
        tcgemm_kernel<<<dim3(8, 20, 1), 256, SMSZ>>>(db, 1024, 2048, 1);
    }
}